// round 16
// baseline (speedup 1.0000x reference)
#include <cuda_runtime.h>
#include <cuda_fp16.h>
#include <cstdint>

#define NUM_EMBED 8192
#define ED 64
#define NTOK 32768
#define CH_STRIDE 4096
#define B_STRIDE 262144

#define OFF_LOSS 2097152
#define OFF_IDX  2097153
#define OFF_BIN  (2097153 + 32768)

#define MCTA 32                      /* tokens per CTA */
#define NBLK (NTOK / MCTA)           /* 1024 */
#define KB 128                       /* codes per tile */
#define NTILES (NUM_EMBED / KB)      /* 64 */
#define CAP 96                       /* candidate slots per token */
#define WWIN 0.070f                  /* rigorous fp16-dot window */

__device__ float g_cnorm[NUM_EMBED * ED];                 // [k][c] normalized codebook fp32
__device__ __align__(16) uint32_t g_Wh[32 * NUM_EMBED];   // [c2][k] half2 channel-pairs
__device__ float g_partial[NBLK];
__device__ unsigned int g_done;

// ===================== PTX helpers =====================
__device__ __forceinline__ uint32_t smem_u32(const void* p) {
    uint32_t a;
    asm("{ .reg .u64 t; cvta.to.shared.u64 t, %1; cvt.u32.u64 %0, t; }" : "=r"(a) : "l"(p));
    return a;
}
#define CP_ASYNC16(dst, src) asm volatile("cp.async.cg.shared.global [%0], [%1], 16;" :: "r"(dst), "l"(src))
#define CP_COMMIT()          asm volatile("cp.async.commit_group;" ::: "memory")
#define CP_WAIT0()           asm volatile("cp.async.wait_group 0;" ::: "memory")

__device__ __forceinline__ __half2 u2h(uint32_t u) {
    __half2 h; *reinterpret_cast<uint32_t*>(&h) = u; return h;
}

// exact warp-wide float max via monotone u32 map + single redux instruction
__device__ __forceinline__ float warp_max_f(float x) {
    uint32_t u = __float_as_uint(x);
    u = (u & 0x80000000u) ? ~u : (u | 0x80000000u);
    uint32_t m;
    asm("redux.sync.max.u32 %0, %1, 0xffffffff;" : "=r"(m) : "r"(u));
    return __uint_as_float((m & 0x80000000u) ? (m & 0x7fffffffu) : ~m);
}

// ===================== prep: normalize + fp16 channel-pair pack + bin zero =====================
__global__ void k_prep_c(const float* __restrict__ ew, float* __restrict__ out_bin) {
    int k = blockIdx.x * 128 + threadIdx.x;
    if (k == 0) g_done = 0u;
    out_bin[k] = 0.f;   // grid covers exactly NUM_EMBED entries
    float v[64]; float ss = 0.f;
#pragma unroll
    for (int i = 0; i < 16; ++i) {
        float4 q = ((const float4*)(ew + (size_t)k * ED))[i];
        v[4*i+0] = q.x; v[4*i+1] = q.y; v[4*i+2] = q.z; v[4*i+3] = q.w;
        ss = fmaf(q.x, q.x, ss); ss = fmaf(q.y, q.y, ss);
        ss = fmaf(q.z, q.z, ss); ss = fmaf(q.w, q.w, ss);
    }
    float nm = fmaxf(__fsqrt_rn(ss), 1e-12f);
    float xn[64];
#pragma unroll
    for (int c = 0; c < 64; ++c) {
        xn[c] = __fdiv_rn(v[c], nm);
        g_cnorm[(size_t)k * ED + c] = xn[c];
    }
#pragma unroll
    for (int c2 = 0; c2 < 32; ++c2) {
        __half2 h = __floats2half2_rn(xn[2*c2], xn[2*c2+1]);
        g_Wh[c2 * NUM_EMBED + k] = *reinterpret_cast<uint32_t*>(&h);
    }
}

// ===================== megakernel =====================
// CTA: 32 tokens, 128 threads; warp owns 8 tokens, lane owns 4 codes per KB=128 tile.
// Raw z staged in WH1 during setup; epilogue re-reads raw z from global -> occ 4.
// Last CTA (fence+ticket) finalizes the loss (same sequential order as old k4).
#define SM_WH0  0                     /* 32*128*4 = 16384 */
#define SM_WH1  16384                 /* 16384 (stage raw z here during setup) */
#define SM_ZH   32768                 /* 32*32*4 = 4096 half2 z [c2][t] */
#define SM_ZS   36864                 /* 32*68*4 = 8704 normalized z [t][68] */
#define SM_NM   45568                 /* 32*4 */
#define SM_CNT  45696                 /* 32*4 */
#define SM_IDX  45824                 /* 32*4 */
#define SM_CAND 45952                 /* 32*96*2 = 6144 */
#define SM_RED  52096                 /* 128*4 */
#define SM_BV   52608                 /* 128*4 */
#define SM_BI   53120                 /* 128*4 */
#define SM_FLAG 53632                 /* 4 */
#define SM_TOT  53636

__global__ __launch_bounds__(128, 4) void k_main(const float* __restrict__ z,
                                                 const float* __restrict__ ew,
                                                 float* __restrict__ out_zq,
                                                 float* __restrict__ out_idx,
                                                 float* __restrict__ out_bin,
                                                 float* __restrict__ out_loss) {
    extern __shared__ char sm_[];
    uint32_t sbase = smem_u32(sm_);
    uint32_t* zh   = (uint32_t*)(sm_ + SM_ZH);
    float*    zstage = (float*)(sm_ + SM_WH1);    // raw z [c][t], setup only
    float*    zs   = (float*)(sm_ + SM_ZS);
    float*    nm   = (float*)(sm_ + SM_NM);
    int*      cnt  = (int*)(sm_ + SM_CNT);
    int*      idxs = (int*)(sm_ + SM_IDX);
    unsigned short* cand = (unsigned short*)(sm_ + SM_CAND);
    float*    red  = (float*)(sm_ + SM_RED);
    float*    bvr  = (float*)(sm_ + SM_BV);
    int*      bir  = (int*)(sm_ + SM_BI);
    int*      flag = (int*)(sm_ + SM_FLAG);

    const int tid  = threadIdx.x;
    const int warp = tid >> 5;
    const int lane = tid & 31;

    const int tok0 = blockIdx.x * MCTA;
    const int b    = tok0 >> 12;
    const int p0   = tok0 & 4095;
    const float* zb = z + (size_t)b * B_STRIDE + p0;

    // prefetch codebook tile 0 (32 c2-rows x 512B) into WH0
    for (int i = tid; i < 32 * 32; i += 128) {
        int c2 = i >> 5, q = i & 31;
        CP_ASYNC16(sbase + SM_WH0 + (c2 * KB + q * 4) * 4,
                   (const char*)(g_Wh + (size_t)c2 * NUM_EMBED) + q * 16);
    }
    CP_COMMIT();

    if (tid < MCTA) cnt[tid] = 0;

    // stage raw z tile [c][32] in WH1
    for (int i = tid; i < 512; i += 128) {
        int c = i >> 3, q = i & 7;
        float4 v = ((const float4*)(zb + c * CH_STRIDE))[q];
        ((float4*)(zstage + c * 32))[q] = v;
    }
    __syncthreads();

    // per-token norms (identical op order to R1/R4/R11/R14/R15)
    if (tid < MCTA) {
        float ss = 0.f;
        for (int c = 0; c < 64; ++c) {
            float x = zstage[c * 32 + tid];
            ss = fmaf(x, x, ss);
        }
        nm[tid] = fmaxf(__fsqrt_rn(ss), 1e-12f);
    }
    __syncthreads();

    // normalized z [t][68]
    for (int i = tid; i < 64 * 32; i += 128) {
        int t = i & 31, c = i >> 5;
        zs[t * 68 + c] = __fdiv_rn(zstage[c * 32 + t], nm[t]);
    }
    __syncthreads();

    // fp16 channel-pair pack of z: zh[c2][t]   (zstage dead after this sync)
    for (int i = tid; i < 32 * 32; i += 128) {
        int c2 = i >> 5, t = i & 31;
        __half2 h = __floats2half2_rn(zs[t * 68 + 2*c2], zs[t * 68 + 2*c2 + 1]);
        zh[c2 * 32 + t] = *reinterpret_cast<uint32_t*>(&h);
    }
    __syncthreads();

    const int t0 = warp * 8;
    const int kc0 = lane * 4;

    float rmf[8];
#pragma unroll
    for (int t = 0; t < 8; ++t) rmf[t] = -1e30f;

    // ---------------- HFMA2 sweep with rigorous candidate push ----------------
    for (int nt = 0; nt < NTILES; ++nt) {
        CP_WAIT0();
        __syncthreads();

        const uint32_t* wq = (nt & 1) ? (uint32_t*)(sm_ + SM_WH1) : (uint32_t*)(sm_ + SM_WH0);

        if (nt + 1 < NTILES) {
            uint32_t wsN = (nt & 1) ? (sbase + SM_WH0) : (sbase + SM_WH1);
            const char* src0 = (const char*)(g_Wh + (size_t)(nt + 1) * KB);
            for (int i = tid; i < 32 * 32; i += 128) {
                int c2 = i >> 5, q = i & 31;
                CP_ASYNC16(wsN + (c2 * KB + q * 4) * 4,
                           src0 + (size_t)c2 * NUM_EMBED * 4 + q * 16);
            }
            CP_COMMIT();
        }

        __half2 acc[8][4];
#pragma unroll
        for (int t = 0; t < 8; ++t)
#pragma unroll
            for (int c = 0; c < 4; ++c) acc[t][c] = __floats2half2_rn(0.f, 0.f);

#pragma unroll 8
        for (int c2 = 0; c2 < 32; ++c2) {
            const uint32_t* zp = zh + c2 * 32 + t0;
            uint4 a0 = *(const uint4*)(zp + 0);
            uint4 a1 = *(const uint4*)(zp + 4);
            uint4 wb = *(const uint4*)(wq + c2 * KB + kc0);
            __half2 av[8] = {u2h(a0.x), u2h(a0.y), u2h(a0.z), u2h(a0.w),
                             u2h(a1.x), u2h(a1.y), u2h(a1.z), u2h(a1.w)};
            __half2 bv[4] = {u2h(wb.x), u2h(wb.y), u2h(wb.z), u2h(wb.w)};
#pragma unroll
            for (int t = 0; t < 8; ++t)
#pragma unroll
                for (int c = 0; c < 4; ++c)
                    acc[t][c] = __hfma2(av[t], bv[c], acc[t][c]);
        }

        // per-token tile max + window push
        int kbase = nt * KB + kc0;
#pragma unroll
        for (int t = 0; t < 8; ++t) {
            __half2 s0 = __hadd2(acc[t][0], __lowhigh2highlow(acc[t][0]));
            __half2 s1 = __hadd2(acc[t][1], __lowhigh2highlow(acc[t][1]));
            __half2 s2 = __hadd2(acc[t][2], __lowhigh2highlow(acc[t][2]));
            __half2 s3 = __hadd2(acc[t][3], __lowhigh2highlow(acc[t][3]));
            __half2 m2 = __hmax2(__hmax2(s0, s1), __hmax2(s2, s3));
            float flm = __low2float(m2);
            float wm = warp_max_f(flm);
            rmf[t] = fmaxf(rmf[t], wm);
            float thr = rmf[t] - WWIN;
            if (flm >= thr) {   // early-out: this lane holds a candidate (rare)
                float d0 = __low2float(s0), d1 = __low2float(s1);
                float d2 = __low2float(s2), d3 = __low2float(s3);
                if (d0 >= thr) {
                    int pos = atomicAdd(&cnt[t0 + t], 1);
                    if (pos < CAP) cand[(t0 + t) * CAP + pos] = (unsigned short)(kbase + 0);
                }
                if (d1 >= thr) {
                    int pos = atomicAdd(&cnt[t0 + t], 1);
                    if (pos < CAP) cand[(t0 + t) * CAP + pos] = (unsigned short)(kbase + 1);
                }
                if (d2 >= thr) {
                    int pos = atomicAdd(&cnt[t0 + t], 1);
                    if (pos < CAP) cand[(t0 + t) * CAP + pos] = (unsigned short)(kbase + 2);
                }
                if (d3 >= thr) {
                    int pos = atomicAdd(&cnt[t0 + t], 1);
                    if (pos < CAP) cand[(t0 + t) * CAP + pos] = (unsigned short)(kbase + 3);
                }
            }
        }
    }
    __syncthreads();

    // ---------------- exact fp32 resolve (4 threads per token) ----------------
    {
        int tk = tid >> 2, q = tid & 3;
        int n = cnt[tk];
        float bv = -1e30f; int bi = 0x7FFFFFFF;
        if (n <= CAP) {
            const float* za = zs + tk * 68;
            for (int j = q; j < n; j += 4) {
                int k = cand[tk * CAP + j];
                const float4* cr4 = (const float4*)(g_cnorm + (size_t)k * ED);
                float d = 0.f;
#pragma unroll
                for (int m = 0; m < 16; ++m) {
                    float4 u = cr4[m];
                    d = fmaf(za[4*m+0], u.x, d);
                    d = fmaf(za[4*m+1], u.y, d);
                    d = fmaf(za[4*m+2], u.z, d);
                    d = fmaf(za[4*m+3], u.w, d);
                }
                if (d > bv || (d == bv && k < bi)) { bv = d; bi = k; }
            }
        }
#pragma unroll
        for (int off = 1; off <= 2; off <<= 1) {
            float ov = __shfl_xor_sync(0xffffffffu, bv, off);
            int   oi = __shfl_xor_sync(0xffffffffu, bi, off);
            if (ov > bv || (ov == bv && oi < bi)) { bv = ov; bi = oi; }
        }
        if (q == 0) idxs[tk] = bi;
    }
    __syncthreads();

    // overflow backstop: full exact scan (rigor guarantee; ~never triggers)
    for (int tk = 0; tk < MCTA; ++tk) {
        if (cnt[tk] > CAP) {
            const float* za = zs + tk * 68;
            float bv = -1e30f; int bi = 0x7FFFFFFF;
            for (int k = tid; k < NUM_EMBED; k += 128) {
                const float4* cr4 = (const float4*)(g_cnorm + (size_t)k * ED);
                float d = 0.f;
#pragma unroll
                for (int m = 0; m < 16; ++m) {
                    float4 u = cr4[m];
                    d = fmaf(za[4*m+0], u.x, d);
                    d = fmaf(za[4*m+1], u.y, d);
                    d = fmaf(za[4*m+2], u.z, d);
                    d = fmaf(za[4*m+3], u.w, d);
                }
                if (d > bv || (d == bv && k < bi)) { bv = d; bi = k; }
            }
            bvr[tid] = bv; bir[tid] = bi;
            __syncthreads();
            for (int s = 64; s > 0; s >>= 1) {
                if (tid < s) {
                    float v2 = bvr[tid + s]; int i2 = bir[tid + s];
                    if (v2 > bvr[tid] || (v2 == bvr[tid] && i2 < bir[tid])) {
                        bvr[tid] = v2; bir[tid] = i2;
                    }
                }
                __syncthreads();
            }
            if (tid == 0) idxs[tk] = bir[0];
            __syncthreads();
        }
    }
    __syncthreads();

    // ---------------- fused epilogue: gather/STE/loss/idx/bin ----------------
    // raw z re-read from global (coalesced, L2-hot; identical values to staged copy)
    int myidx = idxs[lane];
    const float4* er = (const float4*)(ew + (size_t)myidx * ED + warp * 16);
    float4 e0 = er[0], e1 = er[1], e2 = er[2], e3 = er[3];
    float vals[16] = {e0.x, e0.y, e0.z, e0.w, e1.x, e1.y, e1.z, e1.w,
                      e2.x, e2.y, e2.z, e2.w, e3.x, e3.y, e3.z, e3.w};
    float ssq = 0.f;
#pragma unroll
    for (int j = 0; j < 16; ++j) {
        int ch = warp * 16 + j;
        float zc = zb[(size_t)ch * CH_STRIDE + lane];
        float d  = vals[j] - zc;
        out_zq[(size_t)(b * 64 + ch) * 4096 + p0 + lane] = zc + d;
        ssq = fmaf(d, d, ssq);
    }
    red[tid] = ssq;
    __syncthreads();
    for (int s = 64; s > 0; s >>= 1) {
        if (tid < s) red[tid] += red[tid + s];
        __syncthreads();
    }

    if (tid < MCTA) {
        out_idx[tok0 + tid] = (float)idxs[tid];
        atomicAdd(&out_bin[idxs[tid]], 1.0f);
    }

    // publish partial + fence + ticket; last CTA finalizes loss (same order as old k4)
    if (tid == 0) {
        g_partial[blockIdx.x] = red[0];
        __threadfence();
        unsigned int old = atomicAdd(&g_done, 1u);
        flag[0] = (old == NBLK - 1) ? 1 : 0;
    }
    __syncthreads();
    if (flag[0] && tid < 32) {
        float s = 0.f;
        for (int i = tid * 32; i < tid * 32 + 32; ++i) s += g_partial[i];
#pragma unroll
        for (int off = 16; off > 0; off >>= 1)
            s += __shfl_xor_sync(0xffffffffu, s, off);
        if (tid == 0) {
            float m = s / 2097152.0f;
            out_loss[0] = 0.25f * m + m;
        }
    }
}

extern "C" void kernel_launch(void* const* d_in, const int* in_sizes, int n_in,
                              void* d_out, int out_size) {
    const float* z  = (const float*)d_in[0];
    const float* ew = (const float*)d_in[1];
    float* out      = (float*)d_out;

    float* out_zq   = out;
    float* out_loss = out + OFF_LOSS;
    float* out_idx  = out + OFF_IDX;
    float* out_bin  = out + OFF_BIN;

    k_prep_c<<<NUM_EMBED / 128, 128>>>(ew, out_bin);

    cudaFuncSetAttribute(k_main, cudaFuncAttributeMaxDynamicSharedMemorySize, SM_TOT);
    k_main<<<NBLK, 128, SM_TOT>>>(z, ew, out_zq, out_idx, out_bin, out_loss);
}